// round 6
// baseline (speedup 1.0000x reference)
#include <cuda_runtime.h>

#define CC   2
#define HH   200
#define WW   200
#define NN   200
#define HWN  (HH*WW*NN)
#define N8   (NN/8)                     // 25 groups of 8 n per (h,w)
#define NGROUPS (HH*WW*N8)              // 1,000,000

// Factorized per-axis cell tables (int8):
//   g_cx[w*NN + n] = cx in {0,1}, or -1 if x outside [x1,x2]
//   g_cy[h*NN + n] = cy in {0,1}, or -1 if y outside [y1,y2]
__device__ signed char g_cx[WW * NN];
__device__ signed char g_cy[HH * NN];

__global__ void prep_kernel(const float* __restrict__ rois) {
    int idx = blockIdx.x * blockDim.x + threadIdx.x;   // [0, 2*200*200)
    if (idx >= 2 * WW * NN) return;

    int axis = idx / (WW * NN);     // 0 = x, 1 = y
    int rem  = idx % (WW * NN);
    int p    = rem / NN;            // pixel coord (w or h)
    int n    = rem % NN;

    float lo = rois[4 * n + (axis ? 1 : 0)];   // x1 or y1
    float hi = rois[4 * n + (axis ? 3 : 2)];   // x2 or y2
    float cl = fmaxf(hi - lo, 1.0f);
    // double-precision reciprocal so (p-lo)*s tracks fp32 CC*(p-lo)/cl to ~1 ulp
    float s  = (float)((double)CC / (double)cl);

    float pf = (float)p;
    signed char v = -1;
    if (pf >= lo && pf <= hi) {
        int c = (int)floorf((pf - lo) * s);
        c = min(max(c, 0), CC - 1);
        v = (signed char)c;
    }
    if (axis == 0) g_cx[p * NN + n] = v;
    else           g_cy[p * NN + n] = v;
}

// One thread = one 8-n group (32B output segment). Instead of 8 scalar
// predicated gathers, load each needed plane's 32B sector ONCE via 2x LDG.128
// and distribute by compare-select. DRAM sector traffic identical; L1
// wavefronts and issue slots cut ~4x.
__global__ void __launch_bounds__(256)
crop_split_kernel(const float* __restrict__ data, float* __restrict__ out) {
    int gi = blockIdx.x * 256 + threadIdx.x;
    if (gi >= NGROUPS) return;

    int n8 = gi % N8;
    int hw = gi / N8;
    int w  = hw % WW;
    int h  = hw / WW;
    int base = hw * NN + n8 * 8;     // 32B-aligned

    uint2 cxu = *reinterpret_cast<const uint2*>(g_cx + w * NN + n8 * 8);
    uint2 cyu = *reinterpret_cast<const uint2*>(g_cy + h * NN + n8 * 8);

    // per-n cell code: cy*2+cx in {0..3}, or -1 if outside; plane-presence mask
    int code[8];
    int mask = 0;
    #pragma unroll
    for (int i = 0; i < 8; i++) {
        int cx = (int)(signed char)(((i < 4 ? cxu.x : cxu.y) >> (8 * (i & 3))) & 0xffu);
        int cy = (int)(signed char)(((i < 4 ? cyu.x : cyu.y) >> (8 * (i & 3))) & 0xffu);
        int c  = ((cx | cy) >= 0) ? (cy * CC + cx) : -1;
        code[i] = c;
        if (c >= 0) mask |= (1 << c);
    }

    float v[8] = {0.f, 0.f, 0.f, 0.f, 0.f, 0.f, 0.f, 0.f};

    #pragma unroll
    for (int c = 0; c < CC * CC; c++) {
        if (mask & (1 << c)) {
            const float4* p = reinterpret_cast<const float4*>(
                data + (size_t)c * HWN + base);
            float4 a = __ldg(p);
            float4 b = __ldg(p + 1);
            float arr[8] = {a.x, a.y, a.z, a.w, b.x, b.y, b.z, b.w};
            #pragma unroll
            for (int i = 0; i < 8; i++)
                if (code[i] == c) v[i] = arr[i];
        }
    }

    float4* o = reinterpret_cast<float4*>(out + base);
    o[0] = make_float4(v[0], v[1], v[2], v[3]);
    o[1] = make_float4(v[4], v[5], v[6], v[7]);
}

extern "C" void kernel_launch(void* const* d_in, const int* in_sizes, int n_in,
                              void* d_out, int out_size) {
    const float* data = (const float*)d_in[0];   // (4, H, W, N) fp32
    const float* rois = (const float*)d_in[1];   // (N, 4) fp32
    float* out = (float*)d_out;                  // (H, W, N) fp32

    int prep_elems = 2 * WW * NN;                // 80000
    prep_kernel<<<(prep_elems + 255) / 256, 256>>>(rois);

    int blocks = (NGROUPS + 255) / 256;          // 3907
    crop_split_kernel<<<blocks, 256>>>(data, out);
}

// round 9
// speedup vs baseline: 1.0987x; 1.0987x over previous
#include <cuda_runtime.h>

#define CC   2
#define HH   200
#define WW   200
#define NN   200
#define HWN  (HH*WW*NN)
#define N4   (NN/4)                     // 50 float4 groups per (h,w)
#define TOTAL_THREADS (HH*WW*N4)        // 2,000,000

// Factorized per-axis cell tables (int8):
//   g_cx[w*NN + n] = cx in {0,1}, or -1 if x outside [x1,x2]
//   g_cy[h*NN + n] = cy in {0,1}, or -1 if y outside [y1,y2]
__device__ signed char g_cx[WW * NN];
__device__ signed char g_cy[HH * NN];

__global__ void prep_kernel(const float* __restrict__ rois) {
    int idx = blockIdx.x * blockDim.x + threadIdx.x;   // [0, 2*200*200)
    if (idx >= 2 * WW * NN) return;

    int axis = idx / (WW * NN);     // 0 = x, 1 = y
    int rem  = idx % (WW * NN);
    int p    = rem / NN;            // pixel coord (w or h)
    int n    = rem % NN;

    float lo = rois[4 * n + (axis ? 1 : 0)];   // x1 or y1
    float hi = rois[4 * n + (axis ? 3 : 2)];   // x2 or y2
    float cl = fmaxf(hi - lo, 1.0f);
    // double-precision reciprocal so (p-lo)*s tracks fp32 CC*(p-lo)/cl to ~1 ulp
    float s  = (float)((double)CC / (double)cl);

    float pf = (float)p;
    signed char v = -1;
    if (pf >= lo && pf <= hi) {
        int c = (int)floorf((pf - lo) * s);
        c = min(max(c, 0), CC - 1);
        v = (signed char)c;
    }
    if (axis == 0) g_cx[p * NN + n] = v;
    else           g_cy[p * NN + n] = v;
}

// Scalar gather load with L2 evict_last via cache-hint policy (the static
// .L2::evict_last qualifier is only legal on 256-bit loads on sm_103a).
__device__ __forceinline__ float ldg_evict_last(const float* p,
                                                unsigned long long pol) {
    float v;
    asm volatile("ld.global.nc.L2::cache_hint.f32 %0, [%1], %2;"
                 : "=f"(v) : "l"(p), "l"(pol));
    return v;
}

__global__ void __launch_bounds__(256)
crop_split_kernel(const float* __restrict__ data, float* __restrict__ out) {
    int idx = blockIdx.x * 256 + threadIdx.x;
    if (idx >= TOTAL_THREADS) return;

    unsigned long long pol;
    asm("createpolicy.fractional.L2::evict_last.b64 %0, 1.0;" : "=l"(pol));

    int n4 = idx % N4;          // group of 4 consecutive n
    int hw = idx / N4;          // h*WW + w
    int w  = hw % WW;
    int h  = hw / WW;

    int base = hw * NN + n4 * 4;   // 16B aligned

    // 8 bytes of metadata per 16 bytes of output
    char4 cx4 = *reinterpret_cast<const char4*>(g_cx + w * NN + n4 * 4);
    char4 cy4 = *reinterpret_cast<const char4*>(g_cy + h * NN + n4 * 4);

    signed char cxs[4] = {cx4.x, cx4.y, cx4.z, cx4.w};
    signed char cys[4] = {cy4.x, cy4.y, cy4.z, cy4.w};

    float v[4];
    #pragma unroll
    for (int i = 0; i < 4; i++) {
        int cx = cxs[i];
        int cy = cys[i];
        float val = 0.0f;
        if ((cx | cy) >= 0) {
            int cell = cy * CC + cx;
            val = ldg_evict_last(data + (size_t)cell * HWN + base + i, pol);
        }
        v[i] = val;
    }

    *reinterpret_cast<float4*>(out + base) = make_float4(v[0], v[1], v[2], v[3]);
}

extern "C" void kernel_launch(void* const* d_in, const int* in_sizes, int n_in,
                              void* d_out, int out_size) {
    const float* data = (const float*)d_in[0];   // (4, H, W, N) fp32
    const float* rois = (const float*)d_in[1];   // (N, 4) fp32
    float* out = (float*)d_out;                  // (H, W, N) fp32

    int prep_elems = 2 * WW * NN;                // 80000
    prep_kernel<<<(prep_elems + 255) / 256, 256>>>(rois);

    int blocks = (TOTAL_THREADS + 255) / 256;    // 7813
    crop_split_kernel<<<blocks, 256>>>(data, out);
}

// round 10
// speedup vs baseline: 1.2478x; 1.1358x over previous
#include <cuda_runtime.h>

#define CC   2
#define HH   200
#define WW   200
#define NN   200
#define HWN  (HH*WW*NN)
#define N4   (NN/4)                     // 50 float4 groups per (h,w)
#define NGROUPS (HH*WW*N4)              // 2,000,000
#define GRID_CTAS 1184                  // 148 SMs x 8 CTAs: exactly one wave
#define NTHREADS (GRID_CTAS*256)        // 303,104

// Factorized per-axis cell tables (int8):
//   g_cx[w*NN + n] = cx in {0,1}, or -1 if x outside [x1,x2]
//   g_cy[h*NN + n] = cy in {0,1}, or -1 if y outside [y1,y2]
__device__ signed char g_cx[WW * NN];
__device__ signed char g_cy[HH * NN];

__global__ void prep_kernel(const float* __restrict__ rois) {
    int idx = blockIdx.x * blockDim.x + threadIdx.x;   // [0, 2*200*200)
    if (idx >= 2 * WW * NN) return;

    int axis = idx / (WW * NN);     // 0 = x, 1 = y
    int rem  = idx % (WW * NN);
    int p    = rem / NN;            // pixel coord (w or h)
    int n    = rem % NN;

    float lo = rois[4 * n + (axis ? 1 : 0)];   // x1 or y1
    float hi = rois[4 * n + (axis ? 3 : 2)];   // x2 or y2
    float cl = fmaxf(hi - lo, 1.0f);
    // double-precision reciprocal so (p-lo)*s tracks fp32 CC*(p-lo)/cl to ~1 ulp
    float s  = (float)((double)CC / (double)cl);

    float pf = (float)p;
    signed char v = -1;
    if (pf >= lo && pf <= hi) {
        int c = (int)floorf((pf - lo) * s);
        c = min(max(c, 0), CC - 1);
        v = (signed char)c;
    }
    if (axis == 0) g_cx[p * NN + n] = v;
    else           g_cy[p * NN + n] = v;
}

__device__ __forceinline__ void do_group(int gi,
                                         const float* __restrict__ data,
                                         float* __restrict__ out) {
    int n4 = gi % N4;           // group of 4 consecutive n
    int hw = gi / N4;           // h*WW + w
    int w  = hw % WW;
    int h  = hw / WW;

    int base = hw * NN + n4 * 4;   // 16B aligned

    char4 cx4 = *reinterpret_cast<const char4*>(g_cx + w * NN + n4 * 4);
    char4 cy4 = *reinterpret_cast<const char4*>(g_cy + h * NN + n4 * 4);

    signed char cxs[4] = {cx4.x, cx4.y, cx4.z, cx4.w};
    signed char cys[4] = {cy4.x, cy4.y, cy4.z, cy4.w};

    float v[4];
    #pragma unroll
    for (int i = 0; i < 4; i++) {
        int cx = cxs[i];
        int cy = cys[i];
        float val = 0.0f;
        if ((cx | cy) >= 0) {
            int cell = cy * CC + cx;
            val = __ldg(data + (size_t)cell * HWN + base + i);
        }
        v[i] = val;
    }

    *reinterpret_cast<float4*>(out + base) = make_float4(v[0], v[1], v[2], v[3]);
}

// Persistent single-wave kernel: 1184 CTAs grid-stride over the 2M groups.
// No wave transitions; unroll 2 keeps two groups' loads in flight per thread.
__global__ void __launch_bounds__(256)
crop_split_kernel(const float* __restrict__ data, float* __restrict__ out) {
    int t = blockIdx.x * 256 + threadIdx.x;

    // NGROUPS / NTHREADS = 6.598 -> 6 full strided passes + partial 7th
    int gi = t;
    #pragma unroll 2
    for (int it = 0; it < 6; it++) {
        do_group(gi, data, out);
        gi += NTHREADS;
    }
    if (gi < NGROUPS)
        do_group(gi, data, out);
}

extern "C" void kernel_launch(void* const* d_in, const int* in_sizes, int n_in,
                              void* d_out, int out_size) {
    const float* data = (const float*)d_in[0];   // (4, H, W, N) fp32
    const float* rois = (const float*)d_in[1];   // (N, 4) fp32
    float* out = (float*)d_out;                  // (H, W, N) fp32

    int prep_elems = 2 * WW * NN;                // 80000
    prep_kernel<<<(prep_elems + 255) / 256, 256>>>(rois);

    crop_split_kernel<<<GRID_CTAS, 256>>>(data, out);
}